// round 11
// baseline (speedup 1.0000x reference)
#include <cuda_runtime.h>
#include <cuda_fp16.h>
#include <cstdint>

// ---------------------------------------------------------------------------
// RGCN gather-MM:  out[dst[e]] += feat[src[e]] @ W[etype[e]]
//   E = 1,000,000 edges, N = 100,000 nodes, D_in = D_out = 64, R = 16
//
// Pipeline (4 launches):
//   1. k_prep    : fused  zero(out) + W^T fp16 prep + per-block rel histogram
//   2. k_scan    : parallel column scan -> bases, rel offsets, tile table
//   3. k_scatter : counting-sort (src,dst) by relation
//   4. k_rgcn_mma: persistent grouped GEMM, 128-edge tiles, 8 warps/CTA
//        (256 thr). Warp (wm,wn) owns m-rows 32*wm..+31, n-blocks wn*4..+3.
//        A[128,64] gathered feat rows, fp16 hi/lo split in padded smem
//        B[64,64]  = W[rel]^T fp16, reloaded only on rel change
//        D = Ah*Bh + Al*Bh (fp32 accum, m16n8k16 mma.sync fp16)
//        epilogue: stage D in smem (overlays A), red.global.add.v4.f32
// ---------------------------------------------------------------------------

#define E_MAX    1000000
#define NB_SORT  1024
#define TILE     128
#define BLK      256
#define MAXT     7828       // ceil(E/128) + 15
#define GRID_MMA 608        // persistent; ~13 contiguous tiles per CTA

// ---- static device scratch (allocation is forbidden) ----
__device__ int g_src_s[E_MAX];
__device__ int g_dst_s[E_MAX];
__device__ int g_blockcounts[NB_SORT * 16];
__device__ int g_relofs[17];
__device__ int g_tile_rel[MAXT];
__device__ int g_tile_base[MAXT];
__device__ unsigned short g_Bh[16 * 4096];   // fp16 W^T, [r][n][k]

// ---------------------------------------------------------------------------
// fused: zero out + prep W + per-block relation histogram
__global__ void k_prep(float4* out, int n4, const float* __restrict__ W,
                       const int* __restrict__ et, int E, int chunk) {
    for (int i = blockIdx.x * blockDim.x + threadIdx.x; i < n4;
         i += gridDim.x * blockDim.x)
        out[i] = make_float4(0.f, 0.f, 0.f, 0.f);

    if (blockIdx.x < 16) {
        int r = blockIdx.x;
        for (int idx = threadIdx.x; idx < 4096; idx += blockDim.x) {
            int n = idx >> 6, k = idx & 63;
            g_Bh[r * 4096 + idx] =
                __half_as_ushort(__float2half_rn(W[r * 4096 + k * 64 + n]));
        }
    }

    __shared__ int cnt[16];
    if (threadIdx.x < 16) cnt[threadIdx.x] = 0;
    __syncthreads();
    int lo = blockIdx.x * chunk, hi = min(E, lo + chunk);
    for (int e = lo + threadIdx.x; e < hi; e += blockDim.x)
        atomicAdd(&cnt[et[e]], 1);
    __syncthreads();
    if (threadIdx.x < 16)
        g_blockcounts[blockIdx.x * 16 + threadIdx.x] = cnt[threadIdx.x];
}

// ---------------------------------------------------------------------------
// single block, 512 threads. warp w owns column w; lane l owns a 32-block
// register-resident chunk (no serial LDG chain).
__global__ void k_scan(void) {
    __shared__ int rel_total[16];
    __shared__ int relofs_s[17];
    __shared__ int tileofs_s[17];
    int w = threadIdx.x >> 5, lane = threadIdx.x & 31;

    int vals[32];
    #pragma unroll
    for (int i = 0; i < 32; i++)
        vals[i] = g_blockcounts[(lane * 32 + i) * 16 + w];

    int lane_sum = 0;
    #pragma unroll
    for (int i = 0; i < 32; i++) lane_sum += vals[i];

    int inc = lane_sum;
    #pragma unroll
    for (int d = 1; d < 32; d <<= 1) {
        int t = __shfl_up_sync(0xffffffffu, inc, d);
        if (lane >= d) inc += t;
    }
    int run = inc - lane_sum;

    #pragma unroll
    for (int i = 0; i < 32; i++) {
        int v = vals[i];
        g_blockcounts[(lane * 32 + i) * 16 + w] = run;
        run += v;
    }
    if (lane == 31) rel_total[w] = run;
    __syncthreads();

    if (threadIdx.x == 0) {
        int acc = 0, tacc = 0;
        for (int r = 0; r < 16; r++) {
            relofs_s[r] = acc; tileofs_s[r] = tacc; g_relofs[r] = acc;
            acc  += rel_total[r];
            tacc += (rel_total[r] + TILE - 1) / TILE;
        }
        relofs_s[16] = acc; tileofs_s[16] = tacc; g_relofs[16] = acc;
    }
    __syncthreads();

    int ntiles = tileofs_s[16];
    for (int t = threadIdx.x; t < MAXT; t += blockDim.x) {
        if (t < ntiles) {
            int r = 0;
            while (t >= tileofs_s[r + 1]) r++;
            g_tile_rel[t]  = r;
            g_tile_base[t] = relofs_s[r] + (t - tileofs_s[r]) * TILE;
        } else {
            g_tile_rel[t] = -1;
        }
    }
}

// ---------------------------------------------------------------------------
__global__ void k_scatter(const int* __restrict__ src, const int* __restrict__ dst,
                          const int* __restrict__ et, int E, int chunk) {
    __shared__ int cur[16];
    if (threadIdx.x < 16)
        cur[threadIdx.x] = g_relofs[threadIdx.x] +
                           g_blockcounts[blockIdx.x * 16 + threadIdx.x];
    __syncthreads();
    int lo = blockIdx.x * chunk, hi = min(E, lo + chunk);
    for (int e = lo + threadIdx.x; e < hi; e += blockDim.x) {
        int r = et[e];
        int pos = atomicAdd(&cur[r], 1);
        g_src_s[pos] = src[e];
        g_dst_s[pos] = dst[e];
    }
}

// ---------------------------------------------------------------------------
// fp16 m16n8k16 HMMA (sm_80+ portable)
#define MMA_F16(d, a, b)                                                      \
    asm volatile(                                                             \
        "mma.sync.aligned.m16n8k16.row.col.f32.f16.f16.f32 "                  \
        "{%0,%1,%2,%3}, {%4,%5,%6,%7}, {%8,%9}, {%0,%1,%2,%3};"               \
        : "+f"((d)[0]), "+f"((d)[1]), "+f"((d)[2]), "+f"((d)[3])              \
        : "r"((a)[0]), "r"((a)[1]), "r"((a)[2]), "r"((a)[3]),                 \
          "r"((b)[0]), "r"((b)[1]))

// smem (halves, padded stride 72): Ah 128x72 (18432 B) | Al 18432 B |
// Bh 64x72 (9216 B) | src 512 B | dst 512 B.  D staging (128x68 f32 =
// 34816 B) overlays Ah+Al only; Bh persists across tiles of the same rel.
#define SM_AHI  0
#define SM_ALO  18432
#define SM_BHI  36864
#define SM_SRC  46080
#define SM_DST  46592
#define SMEM_DYN 47104
#define ASTRIDE 72

__global__ __launch_bounds__(BLK, 3) void k_rgcn_mma(const float* __restrict__ feat,
                                                     float* __restrict__ out) {
    extern __shared__ char smb[];
    unsigned short* Ah = (unsigned short*)(smb + SM_AHI);
    unsigned short* Al = (unsigned short*)(smb + SM_ALO);
    unsigned short* Bh = (unsigned short*)(smb + SM_BHI);
    int* srcsh = (int*)(smb + SM_SRC);
    int* dsh   = (int*)(smb + SM_DST);
    float* Dst = (float*)smb;          // epilogue staging (overlays Ah/Al)

    int tid = threadIdx.x, w = tid >> 5, lane = tid & 31;
    int wm = w & 3, wn = w >> 2;       // warp owns m-rows 32*wm..+31, nb wn*4..+3
    int g = lane >> 2, tig = lane & 3;

    const float4* featv = (const float4*)feat;

    int per = (MAXT + GRID_MMA - 1) / GRID_MMA;
    int t0 = blockIdx.x * per, t1 = min(MAXT, t0 + per);
    int cur_rel = -1;

    for (int t = t0; t < t1; t++) {
        int rel = g_tile_rel[t];
        if (rel < 0) break;
        int base = g_tile_base[t];
        int n = min(TILE, g_relofs[rel + 1] - base);

        // stage indices (first 128 threads)
        if (tid < TILE) {
            int ok = tid < n;
            srcsh[tid] = ok ? g_src_s[base + tid] : -1;
            dsh[tid]   = ok ? g_dst_s[base + tid] : -1;
        }
        // copy B (8 KB = 512 uint4 chunks = 2 iters at 256 thr) on rel change
        if (rel != cur_rel) {
            cur_rel = rel;
            #pragma unroll
            for (int c = 0; c < 2; c++) {
                int p8  = tid + c * BLK;
                int idx = p8 * 8;
                int nr = idx >> 6, k = idx & 63;
                *(uint4*)(Bh + nr * ASTRIDE + k) =
                    *(const uint4*)(g_Bh + rel * 4096 + idx);
            }
        }
        __syncthreads();

        // gather + fp16 hi/lo split: 16 lanes per 256B feat row, 8 iters
        #pragma unroll
        for (int it = 0; it < 8; it++) {
            int p = tid + it * BLK;
            int row = p >> 4, f = p & 15;
            int s = srcsh[row];
            float4 v = (s >= 0) ? featv[(long long)s * 16 + f]
                                : make_float4(0.f, 0.f, 0.f, 0.f);
            __half hx = __float2half_rn(v.x), hy = __float2half_rn(v.y);
            __half hz = __float2half_rn(v.z), hw = __float2half_rn(v.w);
            __half lx = __float2half_rn(v.x - __half2float(hx));
            __half ly = __float2half_rn(v.y - __half2float(hy));
            __half lz = __float2half_rn(v.z - __half2float(hz));
            __half lw = __float2half_rn(v.w - __half2float(hw));
            unsigned h01 = (unsigned)__half_as_ushort(hx) |
                           ((unsigned)__half_as_ushort(hy) << 16);
            unsigned h23 = (unsigned)__half_as_ushort(hz) |
                           ((unsigned)__half_as_ushort(hw) << 16);
            unsigned l01 = (unsigned)__half_as_ushort(lx) |
                           ((unsigned)__half_as_ushort(ly) << 16);
            unsigned l23 = (unsigned)__half_as_ushort(lz) |
                           ((unsigned)__half_as_ushort(lw) << 16);
            *(uint2*)(Ah + row * ASTRIDE + f * 4) = make_uint2(h01, h23);
            *(uint2*)(Al + row * ASTRIDE + f * 4) = make_uint2(l01, l23);
        }
        __syncthreads();

        // GEMM: 2 m16 blocks x 4 n8 blocks per warp, 2 passes (hi, lo)
        float acc[2][4][4];
        #pragma unroll
        for (int m = 0; m < 2; m++)
            #pragma unroll
            for (int j = 0; j < 4; j++)
                #pragma unroll
                for (int v = 0; v < 4; v++) acc[m][j][v] = 0.f;

        #pragma unroll
        for (int ks = 0; ks < 4; ks++) {
            int kc = ks * 16 + 2 * tig;
            unsigned ah[2][4], al[2][4];
            #pragma unroll
            for (int m = 0; m < 2; m++) {
                int r0 = (32 * wm + 16 * m + g) * ASTRIDE + kc;
                int r1 = r0 + 8 * ASTRIDE;
                ah[m][0] = *(const unsigned*)(Ah + r0);
                ah[m][1] = *(const unsigned*)(Ah + r1);
                ah[m][2] = *(const unsigned*)(Ah + r0 + 8);
                ah[m][3] = *(const unsigned*)(Ah + r1 + 8);
                al[m][0] = *(const unsigned*)(Al + r0);
                al[m][1] = *(const unsigned*)(Al + r1);
                al[m][2] = *(const unsigned*)(Al + r0 + 8);
                al[m][3] = *(const unsigned*)(Al + r1 + 8);
            }
            #pragma unroll
            for (int j = 0; j < 4; j++) {
                int nb = wn * 4 + j;
                int b0 = (8 * nb + g) * ASTRIDE + kc;
                unsigned bh[2];
                bh[0] = *(const unsigned*)(Bh + b0);
                bh[1] = *(const unsigned*)(Bh + b0 + 8);
                #pragma unroll
                for (int m = 0; m < 2; m++) {
                    MMA_F16(acc[m][j], ah[m], bh);
                    MMA_F16(acc[m][j], al[m], bh);
                }
            }
        }
        __syncthreads();   // done reading A smem; reuse as D staging

        #pragma unroll
        for (int m = 0; m < 2; m++) {
            int r0 = 32 * wm + 16 * m + g;
            #pragma unroll
            for (int j = 0; j < 4; j++) {
                int c = 8 * (wn * 4 + j) + 2 * tig;
                *(float2*)(Dst + r0 * 68 + c) =
                    make_float2(acc[m][j][0], acc[m][j][1]);
                *(float2*)(Dst + (r0 + 8) * 68 + c) =
                    make_float2(acc[m][j][2], acc[m][j][3]);
            }
        }
        __syncthreads();

        // scatter: 2 threads per row, 8 x red.v4 each
        {
            int row = tid >> 1, half = tid & 1;
            if (row < n) {
                float* op = out + (long long)dsh[row] * 64 + half * 32;
                const float4* dr = (const float4*)(Dst + row * 68 + half * 32);
                #pragma unroll
                for (int q = 0; q < 8; q++) {
                    float4 v = dr[q];
                    asm volatile("red.global.add.v4.f32 [%0], {%1, %2, %3, %4};"
                                 :: "l"(op + q * 4),
                                    "f"(v.x), "f"(v.y), "f"(v.z), "f"(v.w)
                                 : "memory");
                }
            }
        }
        __syncthreads();   // staging reused as A next iteration
    }
}

// ---------------------------------------------------------------------------
extern "C" void kernel_launch(void* const* d_in, const int* in_sizes, int n_in,
                              void* d_out, int out_size) {
    const float* feat   = (const float*)d_in[0];   // [N, 64]
    const float* weight = (const float*)d_in[1];   // [16, 64, 64]
    const int*   src    = (const int*)d_in[2];     // [E]
    const int*   dst    = (const int*)d_in[3];     // [E]
    const int*   etyp   = (const int*)d_in[4];     // [E]
    float*       out    = (float*)d_out;           // [N, 64]

    int E = in_sizes[2];
    int n4 = out_size >> 2;
    int chunk = (E + NB_SORT - 1) / NB_SORT;

    cudaFuncSetAttribute(k_rgcn_mma, cudaFuncAttributeMaxDynamicSharedMemorySize,
                         SMEM_DYN);

    k_prep<<<NB_SORT, 256>>>((float4*)out, n4, weight, etyp, E, chunk);
    k_scan<<<1, 512>>>();
    k_scatter<<<NB_SORT, 256>>>(src, dst, etyp, E, chunk);
    k_rgcn_mma<<<GRID_MMA, BLK, SMEM_DYN>>>(feat, out);
}

// round 12
// speedup vs baseline: 1.1117x; 1.1117x over previous
#include <cuda_runtime.h>
#include <cuda_fp16.h>
#include <cstdint>

// ---------------------------------------------------------------------------
// RGCN gather-MM:  out[dst[e]] += feat[src[e]] @ W[etype[e]]
//   E = 1,000,000 edges, N = 100,000 nodes, D_in = D_out = 64, R = 16
//
// Pipeline (4 launches):
//   1. k_prep    : zero(out) + W^T fp16 prep + feat fp16 hi/lo split
//                  + per-block relation histogram
//   2. k_scan    : parallel column scan -> bases, rel offsets, tile table
//   3. k_scatter : counting-sort (src,dst) by relation
//   4. k_rgcn_mma: persistent grouped GEMM, 128-edge tiles, 4 warps/CTA,
//        2-stage cp.async pipeline (prefetch tile t+1 A while computing t).
//        A fp16 hi/lo copied byte-wise from pre-split g_fhi/g_flo.
//        D = Ah*Bh + Al*Bh (fp32 accum, m16n8k16 mma.sync fp16).
//        Epilogue: shfl_xor pairs -> red.global.add.v4.f32, no staging.
// ---------------------------------------------------------------------------

#define E_MAX    1000000
#define N_NODES  100000
#define NB_SORT  1024
#define TILE     128
#define BLK      128
#define MAXT     7828       // ceil(E/128) + 15
#define GRID_MMA 304        // 2 CTAs x 152 SMs, persistent

// ---- static device scratch (allocation is forbidden) ----
__device__ int g_src_s[E_MAX];
__device__ int g_dst_s[E_MAX];
__device__ int g_blockcounts[NB_SORT * 16];
__device__ int g_relofs[17];
__device__ int g_tile_rel[MAXT];
__device__ int g_tile_base[MAXT];
__device__ unsigned short g_Bh[16 * 4096];        // fp16 W^T, [r][n][k]
__device__ unsigned short g_fhi[N_NODES * 64];    // feat fp16 hi
__device__ unsigned short g_flo[N_NODES * 64];    // feat fp16 lo (residual)

// ---------------------------------------------------------------------------
// fused: zero out + prep W + split feat + per-block relation histogram
__global__ void k_prep(float4* out, int n4, const float* __restrict__ W,
                       const float* __restrict__ feat,
                       const int* __restrict__ et, int E, int chunk) {
    int gtid = blockIdx.x * blockDim.x + threadIdx.x;
    int gstr = gridDim.x * blockDim.x;

    for (int i = gtid; i < n4; i += gstr)
        out[i] = make_float4(0.f, 0.f, 0.f, 0.f);

    // feat [N,64] fp32 -> g_fhi/g_flo fp16 (vectorized: one float4 -> 4+4 halves)
    const float4* fv = (const float4*)feat;
    for (int i = gtid; i < N_NODES * 16; i += gstr) {
        float4 v = fv[i];
        __half hx = __float2half_rn(v.x), hy = __float2half_rn(v.y);
        __half hz = __float2half_rn(v.z), hw = __float2half_rn(v.w);
        __half lx = __float2half_rn(v.x - __half2float(hx));
        __half ly = __float2half_rn(v.y - __half2float(hy));
        __half lz = __float2half_rn(v.z - __half2float(hz));
        __half lw = __float2half_rn(v.w - __half2float(hw));
        uint2 hp = make_uint2(
            (unsigned)__half_as_ushort(hx) | ((unsigned)__half_as_ushort(hy) << 16),
            (unsigned)__half_as_ushort(hz) | ((unsigned)__half_as_ushort(hw) << 16));
        uint2 lp = make_uint2(
            (unsigned)__half_as_ushort(lx) | ((unsigned)__half_as_ushort(ly) << 16),
            (unsigned)__half_as_ushort(lz) | ((unsigned)__half_as_ushort(lw) << 16));
        ((uint2*)g_fhi)[i] = hp;
        ((uint2*)g_flo)[i] = lp;
    }

    // W[r] is [k][n] row-major fp32 -> g_Bh[r][n][k] fp16
    if (blockIdx.x < 16) {
        int r = blockIdx.x;
        for (int idx = threadIdx.x; idx < 4096; idx += blockDim.x) {
            int n = idx >> 6, k = idx & 63;
            g_Bh[r * 4096 + idx] =
                __half_as_ushort(__float2half_rn(W[r * 4096 + k * 64 + n]));
        }
    }

    __shared__ int cnt[16];
    if (threadIdx.x < 16) cnt[threadIdx.x] = 0;
    __syncthreads();
    int lo = blockIdx.x * chunk, hi = min(E, lo + chunk);
    for (int e = lo + threadIdx.x; e < hi; e += blockDim.x)
        atomicAdd(&cnt[et[e]], 1);
    __syncthreads();
    if (threadIdx.x < 16)
        g_blockcounts[blockIdx.x * 16 + threadIdx.x] = cnt[threadIdx.x];
}

// ---------------------------------------------------------------------------
// single block, 512 threads. warp w owns column w; lane l owns a 32-block
// register-resident chunk (no serial LDG chain).
__global__ void k_scan(void) {
    __shared__ int rel_total[16];
    __shared__ int relofs_s[17];
    __shared__ int tileofs_s[17];
    int w = threadIdx.x >> 5, lane = threadIdx.x & 31;

    int vals[32];
    #pragma unroll
    for (int i = 0; i < 32; i++)
        vals[i] = g_blockcounts[(lane * 32 + i) * 16 + w];

    int lane_sum = 0;
    #pragma unroll
    for (int i = 0; i < 32; i++) lane_sum += vals[i];

    int inc = lane_sum;
    #pragma unroll
    for (int d = 1; d < 32; d <<= 1) {
        int t = __shfl_up_sync(0xffffffffu, inc, d);
        if (lane >= d) inc += t;
    }
    int run = inc - lane_sum;

    #pragma unroll
    for (int i = 0; i < 32; i++) {
        int v = vals[i];
        g_blockcounts[(lane * 32 + i) * 16 + w] = run;
        run += v;
    }
    if (lane == 31) rel_total[w] = run;
    __syncthreads();

    if (threadIdx.x == 0) {
        int acc = 0, tacc = 0;
        for (int r = 0; r < 16; r++) {
            relofs_s[r] = acc; tileofs_s[r] = tacc; g_relofs[r] = acc;
            acc  += rel_total[r];
            tacc += (rel_total[r] + TILE - 1) / TILE;
        }
        relofs_s[16] = acc; tileofs_s[16] = tacc; g_relofs[16] = acc;
    }
    __syncthreads();

    int ntiles = tileofs_s[16];
    for (int t = threadIdx.x; t < MAXT; t += blockDim.x) {
        if (t < ntiles) {
            int r = 0;
            while (t >= tileofs_s[r + 1]) r++;
            g_tile_rel[t]  = r;
            g_tile_base[t] = relofs_s[r] + (t - tileofs_s[r]) * TILE;
        } else {
            g_tile_rel[t] = -1;
        }
    }
}

// ---------------------------------------------------------------------------
__global__ void k_scatter(const int* __restrict__ src, const int* __restrict__ dst,
                          const int* __restrict__ et, int E, int chunk) {
    __shared__ int cur[16];
    if (threadIdx.x < 16)
        cur[threadIdx.x] = g_relofs[threadIdx.x] +
                           g_blockcounts[blockIdx.x * 16 + threadIdx.x];
    __syncthreads();
    int lo = blockIdx.x * chunk, hi = min(E, lo + chunk);
    for (int e = lo + threadIdx.x; e < hi; e += blockDim.x) {
        int r = et[e];
        int pos = atomicAdd(&cur[r], 1);
        g_src_s[pos] = src[e];
        g_dst_s[pos] = dst[e];
    }
}

// ---------------------------------------------------------------------------
// fp16 m16n8k16 HMMA (sm_80+ portable)
#define MMA_F16(d, a, b)                                                      \
    asm volatile(                                                             \
        "mma.sync.aligned.m16n8k16.row.col.f32.f16.f16.f32 "                  \
        "{%0,%1,%2,%3}, {%4,%5,%6,%7}, {%8,%9}, {%0,%1,%2,%3};"               \
        : "+f"((d)[0]), "+f"((d)[1]), "+f"((d)[2]), "+f"((d)[3])              \
        : "r"((a)[0]), "r"((a)[1]), "r"((a)[2]), "r"((a)[3]),                 \
          "r"((b)[0]), "r"((b)[1]))

#define CPA16(saddr, gaddr, ssz)                                              \
    asm volatile("cp.async.cg.shared.global [%0], [%1], 16, %2;"              \
                 :: "r"(saddr), "l"(gaddr), "r"(ssz))

// smem layout (bytes):
//   stage s (s=0,1) at s*36864: Ah 128x72 halves (18432) | Al (18432)
//   Bh  at 73728 (64x72 halves = 9216)
//   dsh at 82944 (2 stages x 128 int = 1024)
#define STAGE_BYTES 36864
#define SM_BHI  73728
#define SM_DST  82944
#define SMEM_DYN 83968
#define ASTRIDE 72           // halves per A row (144 B, 16B-aligned)

__global__ __launch_bounds__(BLK, 2) void k_rgcn_mma(float* __restrict__ out) {
    extern __shared__ char smb[];
    unsigned short* Bh = (unsigned short*)(smb + SM_BHI);
    int* dsh = (int*)(smb + SM_DST);

    int tid = threadIdx.x, w = tid >> 5, lane = tid & 31;
    int g = lane >> 2, tig = lane & 3;

    uint32_t smbase;
    asm("{ .reg .u64 t; cvta.to.shared.u64 t, %1; cvt.u32.u64 %0, t; }"
        : "=r"(smbase) : "l"(smb));

    int per = (MAXT + GRID_MMA - 1) / GRID_MMA;
    int t0 = blockIdx.x * per, t1 = min(MAXT, t0 + per);
    int cur_rel = -1;

    // ---- prefetch issue for tile tt into stage st (all threads) ----
    auto issue = [&](int tt, int st, int reln) {
        int bs = g_tile_base[tt];
        int nn = min(TILE, g_relofs[reln + 1] - bs);
        int ok = tid < nn;
        int srow = ok ? g_src_s[bs + tid] : 0;
        dsh[st * TILE + tid] = ok ? g_dst_s[bs + tid] : -1;
        unsigned ssz = ok ? 16u : 0u;
        uint32_t dhi = smbase + st * STAGE_BYTES + tid * 144;
        uint32_t dlo = dhi + 18432;
        const char* ghi = (const char*)g_fhi + (size_t)srow * 128;
        const char* glo = (const char*)g_flo + (size_t)srow * 128;
        #pragma unroll
        for (int c = 0; c < 8; c++) {
            CPA16(dhi + c * 16, ghi + c * 16, ssz);
            CPA16(dlo + c * 16, glo + c * 16, ssz);
        }
    };

    // prologue: prefetch first tile
    {
        int rel0 = (t0 < t1) ? g_tile_rel[t0] : -1;
        if (rel0 >= 0) issue(t0, 0, rel0);
        asm volatile("cp.async.commit_group;" ::: "memory");
    }

    for (int t = t0; t < t1; t++) {
        int rel = g_tile_rel[t];
        if (rel < 0) break;
        int st = t & 1;

        asm volatile("cp.async.wait_group 0;" ::: "memory");
        __syncthreads();   // stage st ready everywhere; all done with t-1

        // prefetch tile t+1 into the stage t-1 just vacated
        {
            int tn = t + 1;
            int reln = (tn < t1) ? g_tile_rel[tn] : -1;
            if (reln >= 0) issue(tn, tn & 1, reln);
            asm volatile("cp.async.commit_group;" ::: "memory");
        }

        // B reload on relation change (rare: ~1 per CTA range)
        if (rel != cur_rel) {
            cur_rel = rel;
            #pragma unroll
            for (int c = 0; c < 4; c++) {
                int p8  = tid + c * BLK;            // 512 uint4 chunks
                int idx = p8 * 8;
                int nr = idx >> 6, k = idx & 63;
                *(uint4*)(Bh + nr * ASTRIDE + k) =
                    *(const uint4*)(g_Bh + rel * 4096 + idx);
            }
            __syncthreads();
        }

        const unsigned short* Ah =
            (const unsigned short*)(smb + st * STAGE_BYTES);
        const unsigned short* Al = Ah + 9216;       // +18432 B
        const int* dshs = dsh + st * TILE;

        // GEMM: warp w owns rows [32w,32w+32) = 2 m16 x 8 n8 blocks, 2 passes
        float acc[2][8][4];
        #pragma unroll
        for (int m = 0; m < 2; m++)
            #pragma unroll
            for (int nb = 0; nb < 8; nb++)
                #pragma unroll
                for (int j = 0; j < 4; j++) acc[m][nb][j] = 0.f;

        #pragma unroll
        for (int ks = 0; ks < 4; ks++) {
            int kc = ks * 16 + 2 * tig;
            unsigned ah[2][4], al[2][4];
            #pragma unroll
            for (int m = 0; m < 2; m++) {
                int r0 = (32 * w + 16 * m + g) * ASTRIDE + kc;
                int r1 = r0 + 8 * ASTRIDE;
                ah[m][0] = *(const unsigned*)(Ah + r0);
                ah[m][1] = *(const unsigned*)(Ah + r1);
                ah[m][2] = *(const unsigned*)(Ah + r0 + 8);
                ah[m][3] = *(const unsigned*)(Ah + r1 + 8);
                al[m][0] = *(const unsigned*)(Al + r0);
                al[m][1] = *(const unsigned*)(Al + r1);
                al[m][2] = *(const unsigned*)(Al + r0 + 8);
                al[m][3] = *(const unsigned*)(Al + r1 + 8);
            }
            #pragma unroll
            for (int nb = 0; nb < 8; nb++) {
                int b0 = (8 * nb + g) * ASTRIDE + kc;
                unsigned bh[2];
                bh[0] = *(const unsigned*)(Bh + b0);
                bh[1] = *(const unsigned*)(Bh + b0 + 8);
                #pragma unroll
                for (int m = 0; m < 2; m++) {
                    MMA_F16(acc[m][nb], ah[m], bh);
                    MMA_F16(acc[m][nb], al[m], bh);
                }
            }
        }

        // epilogue: partner-lane (lane^1) shfl -> red.v4, no smem staging
        #pragma unroll
        for (int m = 0; m < 2; m++) {
            int r0 = 32 * w + 16 * m + g;
            int dn0 = dshs[r0];
            int dn1 = dshs[r0 + 8];
            #pragma unroll
            for (int nb = 0; nb < 8; nb++) {
                float c0 = acc[m][nb][0], c1 = acc[m][nb][1];
                float c2 = acc[m][nb][2], c3 = acc[m][nb][3];
                float e0 = __shfl_xor_sync(0xffffffffu, c0, 1);
                float e1 = __shfl_xor_sync(0xffffffffu, c1, 1);
                float e2 = __shfl_xor_sync(0xffffffffu, c2, 1);
                float e3 = __shfl_xor_sync(0xffffffffu, c3, 1);
                if (tig & 1) {
                    // odd lane: row r0+8, cols 8nb + 2(tig-1): (e2,e3,c2,c3)
                    if (dn1 >= 0) {
                        float* op = out + (long long)dn1 * 64 + 8 * nb + 2 * (tig - 1);
                        asm volatile("red.global.add.v4.f32 [%0], {%1, %2, %3, %4};"
                                     :: "l"(op), "f"(e2), "f"(e3), "f"(c2), "f"(c3)
                                     : "memory");
                    }
                } else {
                    // even lane: row r0, cols 8nb + 2tig: (c0,c1,e0,e1)
                    if (dn0 >= 0) {
                        float* op = out + (long long)dn0 * 64 + 8 * nb + 2 * tig;
                        asm volatile("red.global.add.v4.f32 [%0], {%1, %2, %3, %4};"
                                     :: "l"(op), "f"(c0), "f"(c1), "f"(e0), "f"(e1)
                                     : "memory");
                    }
                }
            }
        }
        // no trailing barrier: next iteration's wait+syncthreads protects reuse
    }
}

// ---------------------------------------------------------------------------
extern "C" void kernel_launch(void* const* d_in, const int* in_sizes, int n_in,
                              void* d_out, int out_size) {
    const float* feat   = (const float*)d_in[0];   // [N, 64]
    const float* weight = (const float*)d_in[1];   // [16, 64, 64]
    const int*   src    = (const int*)d_in[2];     // [E]
    const int*   dst    = (const int*)d_in[3];     // [E]
    const int*   etyp   = (const int*)d_in[4];     // [E]
    float*       out    = (float*)d_out;           // [N, 64]

    int E = in_sizes[2];
    int n4 = out_size >> 2;
    int chunk = (E + NB_SORT - 1) / NB_SORT;

    cudaFuncSetAttribute(k_rgcn_mma, cudaFuncAttributeMaxDynamicSharedMemorySize,
                         SMEM_DYN);

    k_prep<<<NB_SORT, 256>>>((float4*)out, n4, weight, feat, etyp, E, chunk);
    k_scan<<<1, 512>>>();
    k_scatter<<<NB_SORT, 256>>>(src, dst, etyp, E, chunk);
    k_rgcn_mma<<<GRID_MMA, BLK, SMEM_DYN>>>(out);
}

// round 14
// speedup vs baseline: 1.5343x; 1.3802x over previous
#include <cuda_runtime.h>
#include <cuda_fp16.h>
#include <cstdint>

// ---------------------------------------------------------------------------
// RGCN gather-MM:  out[dst[e]] += feat[src[e]] @ W[etype[e]]
//   E = 1,000,000 edges, N = 100,000 nodes, D_in = D_out = 64, R = 16
//
// Pipeline (4 launches):
//   1. k_prep    : zero(out) + W^T fp16 prep + feat fp16 convert
//                  + per-block relation histogram
//   2. k_scan    : parallel column scan -> bases, rel offsets, tile table
//   3. k_scatter : counting-sort (src,dst) by relation
//   4. k_rgcn_mma: persistent grouped GEMM, 128-edge tiles, 4 warps/CTA,
//        4 CTAs/SM, 2-stage cp.async pipeline (stage index = tile parity;
//        prologue now honors t0's parity — R13 bug). Single-pass fp16 MMA.
//        Epilogue: shfl_xor pairs -> red.global.add.v4.f32, no staging.
// ---------------------------------------------------------------------------

#define E_MAX    1000000
#define N_NODES  100000
#define NB_SORT  1024
#define TILE     128
#define BLK      128
#define MAXT     7828       // ceil(E/128) + 15
#define GRID_MMA 608        // 4 CTAs x 152 SMs, persistent

// ---- static device scratch (allocation is forbidden) ----
__device__ int g_src_s[E_MAX];
__device__ int g_dst_s[E_MAX];
__device__ int g_blockcounts[NB_SORT * 16];
__device__ int g_relofs[17];
__device__ int g_tile_rel[MAXT];
__device__ int g_tile_base[MAXT];
__device__ unsigned short g_Bh[16 * 4096];        // fp16 W^T, [r][n][k]
__device__ unsigned short g_fh[N_NODES * 64];     // feat fp16

// ---------------------------------------------------------------------------
// fused: zero out + prep W + convert feat + per-block relation histogram
__global__ void k_prep(float4* out, int n4, const float* __restrict__ W,
                       const float* __restrict__ feat,
                       const int* __restrict__ et, int E, int chunk) {
    int gtid = blockIdx.x * blockDim.x + threadIdx.x;
    int gstr = gridDim.x * blockDim.x;

    for (int i = gtid; i < n4; i += gstr)
        out[i] = make_float4(0.f, 0.f, 0.f, 0.f);

    // feat [N,64] fp32 -> g_fh fp16 (one float4 -> 4 halves)
    const float4* fv = (const float4*)feat;
    for (int i = gtid; i < N_NODES * 16; i += gstr) {
        float4 v = fv[i];
        uint2 hp = make_uint2(
            (unsigned)__half_as_ushort(__float2half_rn(v.x)) |
            ((unsigned)__half_as_ushort(__float2half_rn(v.y)) << 16),
            (unsigned)__half_as_ushort(__float2half_rn(v.z)) |
            ((unsigned)__half_as_ushort(__float2half_rn(v.w)) << 16));
        ((uint2*)g_fh)[i] = hp;
    }

    // W[r] is [k][n] row-major fp32 -> g_Bh[r][n][k] fp16
    if (blockIdx.x < 16) {
        int r = blockIdx.x;
        for (int idx = threadIdx.x; idx < 4096; idx += blockDim.x) {
            int n = idx >> 6, k = idx & 63;
            g_Bh[r * 4096 + idx] =
                __half_as_ushort(__float2half_rn(W[r * 4096 + k * 64 + n]));
        }
    }

    __shared__ int cnt[16];
    if (threadIdx.x < 16) cnt[threadIdx.x] = 0;
    __syncthreads();
    int lo = blockIdx.x * chunk, hi = min(E, lo + chunk);
    for (int e = lo + threadIdx.x; e < hi; e += blockDim.x)
        atomicAdd(&cnt[et[e]], 1);
    __syncthreads();
    if (threadIdx.x < 16)
        g_blockcounts[blockIdx.x * 16 + threadIdx.x] = cnt[threadIdx.x];
}

// ---------------------------------------------------------------------------
// single block, 512 threads. warp w owns column w; lane l owns a 32-block
// register-resident chunk (no serial LDG chain).
__global__ void k_scan(void) {
    __shared__ int rel_total[16];
    __shared__ int relofs_s[17];
    __shared__ int tileofs_s[17];
    int w = threadIdx.x >> 5, lane = threadIdx.x & 31;

    int vals[32];
    #pragma unroll
    for (int i = 0; i < 32; i++)
        vals[i] = g_blockcounts[(lane * 32 + i) * 16 + w];

    int lane_sum = 0;
    #pragma unroll
    for (int i = 0; i < 32; i++) lane_sum += vals[i];

    int inc = lane_sum;
    #pragma unroll
    for (int d = 1; d < 32; d <<= 1) {
        int t = __shfl_up_sync(0xffffffffu, inc, d);
        if (lane >= d) inc += t;
    }
    int run = inc - lane_sum;

    #pragma unroll
    for (int i = 0; i < 32; i++) {
        int v = vals[i];
        g_blockcounts[(lane * 32 + i) * 16 + w] = run;
        run += v;
    }
    if (lane == 31) rel_total[w] = run;
    __syncthreads();

    if (threadIdx.x == 0) {
        int acc = 0, tacc = 0;
        for (int r = 0; r < 16; r++) {
            relofs_s[r] = acc; tileofs_s[r] = tacc; g_relofs[r] = acc;
            acc  += rel_total[r];
            tacc += (rel_total[r] + TILE - 1) / TILE;
        }
        relofs_s[16] = acc; tileofs_s[16] = tacc; g_relofs[16] = acc;
    }
    __syncthreads();

    int ntiles = tileofs_s[16];
    for (int t = threadIdx.x; t < MAXT; t += blockDim.x) {
        if (t < ntiles) {
            int r = 0;
            while (t >= tileofs_s[r + 1]) r++;
            g_tile_rel[t]  = r;
            g_tile_base[t] = relofs_s[r] + (t - tileofs_s[r]) * TILE;
        } else {
            g_tile_rel[t] = -1;
        }
    }
}

// ---------------------------------------------------------------------------
__global__ void k_scatter(const int* __restrict__ src, const int* __restrict__ dst,
                          const int* __restrict__ et, int E, int chunk) {
    __shared__ int cur[16];
    if (threadIdx.x < 16)
        cur[threadIdx.x] = g_relofs[threadIdx.x] +
                           g_blockcounts[blockIdx.x * 16 + threadIdx.x];
    __syncthreads();
    int lo = blockIdx.x * chunk, hi = min(E, lo + chunk);
    for (int e = lo + threadIdx.x; e < hi; e += blockDim.x) {
        int r = et[e];
        int pos = atomicAdd(&cur[r], 1);
        g_src_s[pos] = src[e];
        g_dst_s[pos] = dst[e];
    }
}

// ---------------------------------------------------------------------------
// fp16 m16n8k16 HMMA (sm_80+ portable)
#define MMA_F16(d, a, b)                                                      \
    asm volatile(                                                             \
        "mma.sync.aligned.m16n8k16.row.col.f32.f16.f16.f32 "                  \
        "{%0,%1,%2,%3}, {%4,%5,%6,%7}, {%8,%9}, {%0,%1,%2,%3};"               \
        : "+f"((d)[0]), "+f"((d)[1]), "+f"((d)[2]), "+f"((d)[3])              \
        : "r"((a)[0]), "r"((a)[1]), "r"((a)[2]), "r"((a)[3]),                 \
          "r"((b)[0]), "r"((b)[1]))

#define CPA16(saddr, gaddr, ssz)                                              \
    asm volatile("cp.async.cg.shared.global [%0], [%1], 16, %2;"              \
                 :: "r"(saddr), "l"(gaddr), "r"(ssz))

// smem layout (bytes):
//   stage s (s=0,1) at s*18432: Ah 128x72 halves (stride 144 B)
//   Bh  at 36864 (64x72 halves = 9216)
//   dsh at 46080 (2 stages x 128 int = 1024)
#define STAGE_BYTES 18432
#define SM_BHI  36864
#define SM_DST  46080
#define SMEM_DYN 47104
#define ASTRIDE 72           // halves per A row (144 B, 16B-aligned)

__global__ __launch_bounds__(BLK, 4) void k_rgcn_mma(float* __restrict__ out) {
    extern __shared__ char smb[];
    unsigned short* Bh = (unsigned short*)(smb + SM_BHI);
    int* dsh = (int*)(smb + SM_DST);

    int tid = threadIdx.x, w = tid >> 5, lane = tid & 31;
    int g = lane >> 2, tig = lane & 3;

    uint32_t smbase;
    asm("{ .reg .u64 t; cvta.to.shared.u64 t, %1; cvt.u32.u64 %0, t; }"
        : "=r"(smbase) : "l"(smb));

    int per = (MAXT + GRID_MMA - 1) / GRID_MMA;
    int t0 = blockIdx.x * per, t1 = min(MAXT, t0 + per);
    int cur_rel = -1;

    // ---- prefetch issue for tile tt into stage st (all threads) ----
    auto issue = [&](int tt, int st, int reln) {
        int bs = g_tile_base[tt];
        int nn = min(TILE, g_relofs[reln + 1] - bs);
        int ok = tid < nn;
        int srow = ok ? g_src_s[bs + tid] : 0;
        dsh[st * TILE + tid] = ok ? g_dst_s[bs + tid] : -1;
        unsigned ssz = ok ? 16u : 0u;
        uint32_t dhi = smbase + st * STAGE_BYTES + tid * 144;
        const char* ghi = (const char*)g_fh + (size_t)srow * 128;
        #pragma unroll
        for (int c = 0; c < 8; c++)
            CPA16(dhi + c * 16, ghi + c * 16, ssz);
    };

    // prologue: prefetch first tile into stage t0&1 (parity fix vs R13:
    // the loop reads stage t&1, and per=13 makes odd t0 common)
    {
        int rel0 = (t0 < t1) ? g_tile_rel[t0] : -1;
        if (rel0 >= 0) issue(t0, t0 & 1, rel0);
        asm volatile("cp.async.commit_group;" ::: "memory");
    }

    for (int t = t0; t < t1; t++) {
        int rel = g_tile_rel[t];
        if (rel < 0) break;
        int st = t & 1;

        asm volatile("cp.async.wait_group 0;" ::: "memory");
        __syncthreads();   // stage st ready everywhere; all done with t-1

        // prefetch tile t+1 into the stage just vacated
        {
            int tn = t + 1;
            int reln = (tn < t1) ? g_tile_rel[tn] : -1;
            if (reln >= 0) issue(tn, tn & 1, reln);
            asm volatile("cp.async.commit_group;" ::: "memory");
        }

        // B reload on relation change (rare: ~1-2 per CTA range)
        if (rel != cur_rel) {
            cur_rel = rel;
            #pragma unroll
            for (int c = 0; c < 4; c++) {
                int p8  = tid + c * BLK;            // 512 uint4 chunks
                int idx = p8 * 8;
                int nr = idx >> 6, k = idx & 63;
                *(uint4*)(Bh + nr * ASTRIDE + k) =
                    *(const uint4*)(g_Bh + rel * 4096 + idx);
            }
            __syncthreads();
        }

        const unsigned short* Ah =
            (const unsigned short*)(smb + st * STAGE_BYTES);
        const int* dshs = dsh + st * TILE;

        // GEMM: warp w owns rows [32w,32w+32) = 2 m16 x 8 n8 blocks, 1 pass
        float acc[2][8][4];
        #pragma unroll
        for (int m = 0; m < 2; m++)
            #pragma unroll
            for (int nb = 0; nb < 8; nb++)
                #pragma unroll
                for (int j = 0; j < 4; j++) acc[m][nb][j] = 0.f;

        #pragma unroll
        for (int ks = 0; ks < 4; ks++) {
            int kc = ks * 16 + 2 * tig;
            unsigned ah[2][4];
            #pragma unroll
            for (int m = 0; m < 2; m++) {
                int r0 = (32 * w + 16 * m + g) * ASTRIDE + kc;
                int r1 = r0 + 8 * ASTRIDE;
                ah[m][0] = *(const unsigned*)(Ah + r0);
                ah[m][1] = *(const unsigned*)(Ah + r1);
                ah[m][2] = *(const unsigned*)(Ah + r0 + 8);
                ah[m][3] = *(const unsigned*)(Ah + r1 + 8);
            }
            #pragma unroll
            for (int nb = 0; nb < 8; nb++) {
                int b0 = (8 * nb + g) * ASTRIDE + kc;
                unsigned bh[2];
                bh[0] = *(const unsigned*)(Bh + b0);
                bh[1] = *(const unsigned*)(Bh + b0 + 8);
                #pragma unroll
                for (int m = 0; m < 2; m++)
                    MMA_F16(acc[m][nb], ah[m], bh);
            }
        }

        // epilogue: partner-lane (lane^1) shfl -> red.v4, no smem staging
        #pragma unroll
        for (int m = 0; m < 2; m++) {
            int r0 = 32 * w + 16 * m + g;
            int dn0 = dshs[r0];
            int dn1 = dshs[r0 + 8];
            #pragma unroll
            for (int nb = 0; nb < 8; nb++) {
                float c0 = acc[m][nb][0], c1 = acc[m][nb][1];
                float c2 = acc[m][nb][2], c3 = acc[m][nb][3];
                float e0 = __shfl_xor_sync(0xffffffffu, c0, 1);
                float e1 = __shfl_xor_sync(0xffffffffu, c1, 1);
                float e2 = __shfl_xor_sync(0xffffffffu, c2, 1);
                float e3 = __shfl_xor_sync(0xffffffffu, c3, 1);
                if (tig & 1) {
                    if (dn1 >= 0) {
                        float* op = out + (long long)dn1 * 64 + 8 * nb + 2 * (tig - 1);
                        asm volatile("red.global.add.v4.f32 [%0], {%1, %2, %3, %4};"
                                     :: "l"(op), "f"(e2), "f"(e3), "f"(c2), "f"(c3)
                                     : "memory");
                    }
                } else {
                    if (dn0 >= 0) {
                        float* op = out + (long long)dn0 * 64 + 8 * nb + 2 * tig;
                        asm volatile("red.global.add.v4.f32 [%0], {%1, %2, %3, %4};"
                                     :: "l"(op), "f"(c0), "f"(c1), "f"(e0), "f"(e1)
                                     : "memory");
                    }
                }
            }
        }
        // no trailing barrier: next iteration's wait+syncthreads protects reuse
    }
}

// ---------------------------------------------------------------------------
extern "C" void kernel_launch(void* const* d_in, const int* in_sizes, int n_in,
                              void* d_out, int out_size) {
    const float* feat   = (const float*)d_in[0];   // [N, 64]
    const float* weight = (const float*)d_in[1];   // [16, 64, 64]
    const int*   src    = (const int*)d_in[2];     // [E]
    const int*   dst    = (const int*)d_in[3];     // [E]
    const int*   etyp   = (const int*)d_in[4];     // [E]
    float*       out    = (float*)d_out;           // [N, 64]

    int E = in_sizes[2];
    int n4 = out_size >> 2;
    int chunk = (E + NB_SORT - 1) / NB_SORT;

    cudaFuncSetAttribute(k_rgcn_mma, cudaFuncAttributeMaxDynamicSharedMemorySize,
                         SMEM_DYN);

    k_prep<<<NB_SORT, 256>>>((float4*)out, n4, weight, feat, etyp, E, chunk);
    k_scan<<<1, 512>>>();
    k_scatter<<<NB_SORT, 256>>>(src, dst, etyp, E, chunk);
    k_rgcn_mma<<<GRID_MMA, BLK, SMEM_DYN>>>(out);
}

// round 15
// speedup vs baseline: 1.7347x; 1.1306x over previous
#include <cuda_runtime.h>
#include <cuda_fp16.h>
#include <cstdint>

// ---------------------------------------------------------------------------
// RGCN gather-MM:  out[dst[e]] += feat[src[e]] @ W[etype[e]]
//   E = 1,000,000 edges, N = 100,000 nodes, D_in = D_out = 64, R = 16
//
// Pipeline (4 launches):
//   1. k_prep    : zero(out) + W^T fp16 prep + feat fp16 convert
//                  + per-block relation histogram
//   2. k_scan    : parallel column scan -> bases, rel offsets, tile table
//   3. k_scatter : counting-sort packed (src,dst) int2 by relation
//   4. k_rgcn_mma: persistent grouped GEMM, 128-edge tiles, 4 warps/CTA,
//        4 CTAs/SM, 2-stage cp.async pipeline. Row-cooperative gather
//        (8 lanes x 16B per 128B feat row -> 4 L1 lines per warp-instr
//        instead of 32). Single-pass fp16 MMA.
//        Epilogue: shfl_xor pairs -> red.global.add.v4.f32, no staging.
// ---------------------------------------------------------------------------

#define E_MAX    1000000
#define N_NODES  100000
#define NB_SORT  1024
#define TILE     128
#define BLK      128
#define MAXT     7828       // ceil(E/128) + 15
#define GRID_MMA 608        // 4 CTAs x 152 SMs, persistent

// ---- static device scratch (allocation is forbidden) ----
__device__ int2 g_edge[E_MAX];                    // packed (src, dst), rel-sorted
__device__ int g_blockcounts[NB_SORT * 16];
__device__ int g_relofs[17];
__device__ int g_tile_rel[MAXT];
__device__ int g_tile_base[MAXT];
__device__ unsigned short g_Bh[16 * 4096];        // fp16 W^T, [r][n][k]
__device__ unsigned short g_fh[N_NODES * 64];     // feat fp16

// ---------------------------------------------------------------------------
// fused: zero out + prep W + convert feat + per-block relation histogram
__global__ void k_prep(float4* out, int n4, const float* __restrict__ W,
                       const float* __restrict__ feat,
                       const int* __restrict__ et, int E, int chunk) {
    int gtid = blockIdx.x * blockDim.x + threadIdx.x;
    int gstr = gridDim.x * blockDim.x;

    for (int i = gtid; i < n4; i += gstr)
        out[i] = make_float4(0.f, 0.f, 0.f, 0.f);

    // feat [N,64] fp32 -> g_fh fp16 (one float4 -> 4 halves)
    const float4* fv = (const float4*)feat;
    for (int i = gtid; i < N_NODES * 16; i += gstr) {
        float4 v = fv[i];
        uint2 hp = make_uint2(
            (unsigned)__half_as_ushort(__float2half_rn(v.x)) |
            ((unsigned)__half_as_ushort(__float2half_rn(v.y)) << 16),
            (unsigned)__half_as_ushort(__float2half_rn(v.z)) |
            ((unsigned)__half_as_ushort(__float2half_rn(v.w)) << 16));
        ((uint2*)g_fh)[i] = hp;
    }

    // W[r] is [k][n] row-major fp32 -> g_Bh[r][n][k] fp16
    if (blockIdx.x < 16) {
        int r = blockIdx.x;
        for (int idx = threadIdx.x; idx < 4096; idx += blockDim.x) {
            int n = idx >> 6, k = idx & 63;
            g_Bh[r * 4096 + idx] =
                __half_as_ushort(__float2half_rn(W[r * 4096 + k * 64 + n]));
        }
    }

    __shared__ int cnt[16];
    if (threadIdx.x < 16) cnt[threadIdx.x] = 0;
    __syncthreads();
    int lo = blockIdx.x * chunk, hi = min(E, lo + chunk);
    for (int e = lo + threadIdx.x; e < hi; e += blockDim.x)
        atomicAdd(&cnt[et[e]], 1);
    __syncthreads();
    if (threadIdx.x < 16)
        g_blockcounts[blockIdx.x * 16 + threadIdx.x] = cnt[threadIdx.x];
}

// ---------------------------------------------------------------------------
// single block, 512 threads. warp w owns column w; lane l owns a 32-block
// register-resident chunk (no serial LDG chain).
__global__ void k_scan(void) {
    __shared__ int rel_total[16];
    __shared__ int relofs_s[17];
    __shared__ int tileofs_s[17];
    int w = threadIdx.x >> 5, lane = threadIdx.x & 31;

    int vals[32];
    #pragma unroll
    for (int i = 0; i < 32; i++)
        vals[i] = g_blockcounts[(lane * 32 + i) * 16 + w];

    int lane_sum = 0;
    #pragma unroll
    for (int i = 0; i < 32; i++) lane_sum += vals[i];

    int inc = lane_sum;
    #pragma unroll
    for (int d = 1; d < 32; d <<= 1) {
        int t = __shfl_up_sync(0xffffffffu, inc, d);
        if (lane >= d) inc += t;
    }
    int run = inc - lane_sum;

    #pragma unroll
    for (int i = 0; i < 32; i++) {
        int v = vals[i];
        g_blockcounts[(lane * 32 + i) * 16 + w] = run;
        run += v;
    }
    if (lane == 31) rel_total[w] = run;
    __syncthreads();

    if (threadIdx.x == 0) {
        int acc = 0, tacc = 0;
        for (int r = 0; r < 16; r++) {
            relofs_s[r] = acc; tileofs_s[r] = tacc; g_relofs[r] = acc;
            acc  += rel_total[r];
            tacc += (rel_total[r] + TILE - 1) / TILE;
        }
        relofs_s[16] = acc; tileofs_s[16] = tacc; g_relofs[16] = acc;
    }
    __syncthreads();

    int ntiles = tileofs_s[16];
    for (int t = threadIdx.x; t < MAXT; t += blockDim.x) {
        if (t < ntiles) {
            int r = 0;
            while (t >= tileofs_s[r + 1]) r++;
            g_tile_rel[t]  = r;
            g_tile_base[t] = relofs_s[r] + (t - tileofs_s[r]) * TILE;
        } else {
            g_tile_rel[t] = -1;
        }
    }
}

// ---------------------------------------------------------------------------
__global__ void k_scatter(const int* __restrict__ src, const int* __restrict__ dst,
                          const int* __restrict__ et, int E, int chunk) {
    __shared__ int cur[16];
    if (threadIdx.x < 16)
        cur[threadIdx.x] = g_relofs[threadIdx.x] +
                           g_blockcounts[blockIdx.x * 16 + threadIdx.x];
    __syncthreads();
    int lo = blockIdx.x * chunk, hi = min(E, lo + chunk);
    for (int e = lo + threadIdx.x; e < hi; e += blockDim.x) {
        int r = et[e];
        int pos = atomicAdd(&cur[r], 1);
        g_edge[pos] = make_int2(src[e], dst[e]);   // one 8B store (1 sector)
    }
}

// ---------------------------------------------------------------------------
// fp16 m16n8k16 HMMA (sm_80+ portable)
#define MMA_F16(d, a, b)                                                      \
    asm volatile(                                                             \
        "mma.sync.aligned.m16n8k16.row.col.f32.f16.f16.f32 "                  \
        "{%0,%1,%2,%3}, {%4,%5,%6,%7}, {%8,%9}, {%0,%1,%2,%3};"               \
        : "+f"((d)[0]), "+f"((d)[1]), "+f"((d)[2]), "+f"((d)[3])              \
        : "r"((a)[0]), "r"((a)[1]), "r"((a)[2]), "r"((a)[3]),                 \
          "r"((b)[0]), "r"((b)[1]))

#define CPA16(saddr, gaddr, ssz)                                              \
    asm volatile("cp.async.cg.shared.global [%0], [%1], 16, %2;"              \
                 :: "r"(saddr), "l"(gaddr), "r"(ssz))

// smem layout (bytes):
//   stage s (s=0,1) at s*18432: Ah 128x72 halves (stride 144 B)
//   Bh  at 36864 (64x72 halves = 9216)
//   dsh at 46080 (2 stages x 128 int = 1024)
#define STAGE_BYTES 18432
#define SM_BHI  36864
#define SM_DST  46080
#define SMEM_DYN 47104
#define ASTRIDE 72           // halves per A row (144 B, 16B-aligned)

__global__ __launch_bounds__(BLK, 4) void k_rgcn_mma(float* __restrict__ out) {
    extern __shared__ char smb[];
    unsigned short* Bh = (unsigned short*)(smb + SM_BHI);
    int* dsh = (int*)(smb + SM_DST);

    int tid = threadIdx.x, w = tid >> 5, lane = tid & 31;
    int g = lane >> 2, tig = lane & 3;

    uint32_t smbase;
    asm("{ .reg .u64 t; cvta.to.shared.u64 t, %1; cvt.u32.u64 %0, t; }"
        : "=r"(smbase) : "l"(smb));

    int per = (MAXT + GRID_MMA - 1) / GRID_MMA;
    int t0 = blockIdx.x * per, t1 = min(MAXT, t0 + per);
    int cur_rel = -1;

    // ---- prefetch tile tt into stage st: 8 lanes cooperate per feat row,
    //      so each warp-instruction touches 4 whole 128B lines (4 L1 wf),
    //      not 32 scattered lines. ----
    int rsub = tid >> 3, ch = tid & 7;     // rsub: 0..15, ch: 0..7 (16B chunk)
    auto issue = [&](int tt, int st, int reln) {
        int bs = g_tile_base[tt];
        int nn = min(TILE, g_relofs[reln + 1] - bs);
        #pragma unroll
        for (int it = 0; it < 8; it++) {
            int row = it * 16 + rsub;
            int ok = row < nn;
            int2 e = ok ? g_edge[bs + row] : make_int2(0, -1);
            if (ch == 0) dsh[st * TILE + row] = ok ? e.y : -1;
            unsigned ssz = ok ? 16u : 0u;
            uint32_t d = smbase + st * STAGE_BYTES + row * 144 + ch * 16;
            CPA16(d, (const char*)g_fh + (size_t)e.x * 128 + ch * 16, ssz);
        }
    };

    // prologue: prefetch first tile into stage t0&1 (parity-correct)
    {
        int rel0 = (t0 < t1) ? g_tile_rel[t0] : -1;
        if (rel0 >= 0) issue(t0, t0 & 1, rel0);
        asm volatile("cp.async.commit_group;" ::: "memory");
    }

    for (int t = t0; t < t1; t++) {
        int rel = g_tile_rel[t];
        if (rel < 0) break;
        int st = t & 1;

        asm volatile("cp.async.wait_group 0;" ::: "memory");
        __syncthreads();   // stage st ready everywhere; all done with t-1

        // prefetch tile t+1 into the stage just vacated
        {
            int tn = t + 1;
            int reln = (tn < t1) ? g_tile_rel[tn] : -1;
            if (reln >= 0) issue(tn, tn & 1, reln);
            asm volatile("cp.async.commit_group;" ::: "memory");
        }

        // B reload on relation change (rare: ~1-2 per CTA range)
        if (rel != cur_rel) {
            cur_rel = rel;
            #pragma unroll
            for (int c = 0; c < 4; c++) {
                int p8  = tid + c * BLK;            // 512 uint4 chunks
                int idx = p8 * 8;
                int nr = idx >> 6, k = idx & 63;
                *(uint4*)(Bh + nr * ASTRIDE + k) =
                    *(const uint4*)(g_Bh + rel * 4096 + idx);
            }
            __syncthreads();
        }

        const unsigned short* Ah =
            (const unsigned short*)(smb + st * STAGE_BYTES);
        const int* dshs = dsh + st * TILE;

        // GEMM: warp w owns rows [32w,32w+32) = 2 m16 x 8 n8 blocks, 1 pass
        float acc[2][8][4];
        #pragma unroll
        for (int m = 0; m < 2; m++)
            #pragma unroll
            for (int nb = 0; nb < 8; nb++)
                #pragma unroll
                for (int j = 0; j < 4; j++) acc[m][nb][j] = 0.f;

        #pragma unroll
        for (int ks = 0; ks < 4; ks++) {
            int kc = ks * 16 + 2 * tig;
            unsigned ah[2][4];
            #pragma unroll
            for (int m = 0; m < 2; m++) {
                int r0 = (32 * w + 16 * m + g) * ASTRIDE + kc;
                int r1 = r0 + 8 * ASTRIDE;
                ah[m][0] = *(const unsigned*)(Ah + r0);
                ah[m][1] = *(const unsigned*)(Ah + r1);
                ah[m][2] = *(const unsigned*)(Ah + r0 + 8);
                ah[m][3] = *(const unsigned*)(Ah + r1 + 8);
            }
            #pragma unroll
            for (int nb = 0; nb < 8; nb++) {
                int b0 = (8 * nb + g) * ASTRIDE + kc;
                unsigned bh[2];
                bh[0] = *(const unsigned*)(Bh + b0);
                bh[1] = *(const unsigned*)(Bh + b0 + 8);
                #pragma unroll
                for (int m = 0; m < 2; m++)
                    MMA_F16(acc[m][nb], ah[m], bh);
            }
        }

        // epilogue: partner-lane (lane^1) shfl -> red.v4, no smem staging
        #pragma unroll
        for (int m = 0; m < 2; m++) {
            int r0 = 32 * w + 16 * m + g;
            int dn0 = dshs[r0];
            int dn1 = dshs[r0 + 8];
            #pragma unroll
            for (int nb = 0; nb < 8; nb++) {
                float c0 = acc[m][nb][0], c1 = acc[m][nb][1];
                float c2 = acc[m][nb][2], c3 = acc[m][nb][3];
                float e0 = __shfl_xor_sync(0xffffffffu, c0, 1);
                float e1 = __shfl_xor_sync(0xffffffffu, c1, 1);
                float e2 = __shfl_xor_sync(0xffffffffu, c2, 1);
                float e3 = __shfl_xor_sync(0xffffffffu, c3, 1);
                if (tig & 1) {
                    if (dn1 >= 0) {
                        float* op = out + (long long)dn1 * 64 + 8 * nb + 2 * (tig - 1);
                        asm volatile("red.global.add.v4.f32 [%0], {%1, %2, %3, %4};"
                                     :: "l"(op), "f"(e2), "f"(e3), "f"(c2), "f"(c3)
                                     : "memory");
                    }
                } else {
                    if (dn0 >= 0) {
                        float* op = out + (long long)dn0 * 64 + 8 * nb + 2 * tig;
                        asm volatile("red.global.add.v4.f32 [%0], {%1, %2, %3, %4};"
                                     :: "l"(op), "f"(c0), "f"(c1), "f"(e0), "f"(e1)
                                     : "memory");
                    }
                }
            }
        }
        // no trailing barrier: next iteration's wait+syncthreads protects reuse
    }
}

// ---------------------------------------------------------------------------
extern "C" void kernel_launch(void* const* d_in, const int* in_sizes, int n_in,
                              void* d_out, int out_size) {
    const float* feat   = (const float*)d_in[0];   // [N, 64]
    const float* weight = (const float*)d_in[1];   // [16, 64, 64]
    const int*   src    = (const int*)d_in[2];     // [E]
    const int*   dst    = (const int*)d_in[3];     // [E]
    const int*   etyp   = (const int*)d_in[4];     // [E]
    float*       out    = (float*)d_out;           // [N, 64]

    int E = in_sizes[2];
    int n4 = out_size >> 2;
    int chunk = (E + NB_SORT - 1) / NB_SORT;

    cudaFuncSetAttribute(k_rgcn_mma, cudaFuncAttributeMaxDynamicSharedMemorySize,
                         SMEM_DYN);

    k_prep<<<NB_SORT, 256>>>((float4*)out, n4, weight, feat, etyp, E, chunk);
    k_scan<<<1, 512>>>();
    k_scatter<<<NB_SORT, 256>>>(src, dst, etyp, E, chunk);
    k_rgcn_mma<<<GRID_MMA, BLK, SMEM_DYN>>>(out);
}

// round 16
// speedup vs baseline: 1.7639x; 1.0169x over previous
#include <cuda_runtime.h>
#include <cuda_fp16.h>
#include <cstdint>

// ---------------------------------------------------------------------------
// RGCN gather-MM:  out[dst[e]] += feat[src[e]] @ W[etype[e]]
//   E = 1,000,000 edges, N = 100,000 nodes, D_in = D_out = 64, R = 16
//
// Pipeline (4 launches):
//   1. k_prep    : zero(out) + W^T fp16 prep + feat fp16 convert
//                  + per-block relation histogram
//   2. k_scan    : parallel column scan -> bases, rel offsets, tile table
//   3. k_scatter : counting-sort packed (src,dst) int2 by relation
//   4. k_rgcn_mma: persistent grouped GEMM, 128-edge tiles, 4 warps/CTA,
//        5 CTAs/SM (XOR-swizzled dense A stages, no padding; regs capped
//        via launch_bounds), 2-stage cp.async pipeline, row-cooperative
//        gather. Single-pass fp16 MMA.
//        Epilogue: shfl_xor pairs -> red.global.add.v4.f32, no staging.
// ---------------------------------------------------------------------------

#define E_MAX    1000000
#define N_NODES  100000
#define NB_SORT  1024
#define TILE     128
#define BLK      128
#define MAXT     7828       // ceil(E/128) + 15
#define GRID_MMA 760        // 5 CTAs x 152 SMs, persistent

// ---- static device scratch (allocation is forbidden) ----
__device__ int2 g_edge[E_MAX];                    // packed (src, dst), rel-sorted
__device__ int g_blockcounts[NB_SORT * 16];
__device__ int g_relofs[17];
__device__ int g_tile_rel[MAXT];
__device__ int g_tile_base[MAXT];
__device__ unsigned short g_Bh[16 * 4096];        // fp16 W^T, [r][n][k]
__device__ unsigned short g_fh[N_NODES * 64];     // feat fp16

// ---------------------------------------------------------------------------
// fused: zero out + prep W + convert feat + per-block relation histogram
__global__ void k_prep(float4* out, int n4, const float* __restrict__ W,
                       const float* __restrict__ feat,
                       const int* __restrict__ et, int E, int chunk) {
    int gtid = blockIdx.x * blockDim.x + threadIdx.x;
    int gstr = gridDim.x * blockDim.x;

    for (int i = gtid; i < n4; i += gstr)
        out[i] = make_float4(0.f, 0.f, 0.f, 0.f);

    // feat [N,64] fp32 -> g_fh fp16 (one float4 -> 4 halves)
    const float4* fv = (const float4*)feat;
    for (int i = gtid; i < N_NODES * 16; i += gstr) {
        float4 v = fv[i];
        uint2 hp = make_uint2(
            (unsigned)__half_as_ushort(__float2half_rn(v.x)) |
            ((unsigned)__half_as_ushort(__float2half_rn(v.y)) << 16),
            (unsigned)__half_as_ushort(__float2half_rn(v.z)) |
            ((unsigned)__half_as_ushort(__float2half_rn(v.w)) << 16));
        ((uint2*)g_fh)[i] = hp;
    }

    // W[r] is [k][n] row-major fp32 -> g_Bh[r][n][k] fp16
    if (blockIdx.x < 16) {
        int r = blockIdx.x;
        for (int idx = threadIdx.x; idx < 4096; idx += blockDim.x) {
            int n = idx >> 6, k = idx & 63;
            g_Bh[r * 4096 + idx] =
                __half_as_ushort(__float2half_rn(W[r * 4096 + k * 64 + n]));
        }
    }

    __shared__ int cnt[16];
    if (threadIdx.x < 16) cnt[threadIdx.x] = 0;
    __syncthreads();
    int lo = blockIdx.x * chunk, hi = min(E, lo + chunk);
    for (int e = lo + threadIdx.x; e < hi; e += blockDim.x)
        atomicAdd(&cnt[et[e]], 1);
    __syncthreads();
    if (threadIdx.x < 16)
        g_blockcounts[blockIdx.x * 16 + threadIdx.x] = cnt[threadIdx.x];
}

// ---------------------------------------------------------------------------
// single block, 512 threads. warp w owns column w; lane l owns a 32-block
// register-resident chunk (no serial LDG chain).
__global__ void k_scan(void) {
    __shared__ int rel_total[16];
    __shared__ int relofs_s[17];
    __shared__ int tileofs_s[17];
    int w = threadIdx.x >> 5, lane = threadIdx.x & 31;

    int vals[32];
    #pragma unroll
    for (int i = 0; i < 32; i++)
        vals[i] = g_blockcounts[(lane * 32 + i) * 16 + w];

    int lane_sum = 0;
    #pragma unroll
    for (int i = 0; i < 32; i++) lane_sum += vals[i];

    int inc = lane_sum;
    #pragma unroll
    for (int d = 1; d < 32; d <<= 1) {
        int t = __shfl_up_sync(0xffffffffu, inc, d);
        if (lane >= d) inc += t;
    }
    int run = inc - lane_sum;

    #pragma unroll
    for (int i = 0; i < 32; i++) {
        int v = vals[i];
        g_blockcounts[(lane * 32 + i) * 16 + w] = run;
        run += v;
    }
    if (lane == 31) rel_total[w] = run;
    __syncthreads();

    if (threadIdx.x == 0) {
        int acc = 0, tacc = 0;
        for (int r = 0; r < 16; r++) {
            relofs_s[r] = acc; tileofs_s[r] = tacc; g_relofs[r] = acc;
            acc  += rel_total[r];
            tacc += (rel_total[r] + TILE - 1) / TILE;
        }
        relofs_s[16] = acc; tileofs_s[16] = tacc; g_relofs[16] = acc;
    }
    __syncthreads();

    int ntiles = tileofs_s[16];
    for (int t = threadIdx.x; t < MAXT; t += blockDim.x) {
        if (t < ntiles) {
            int r = 0;
            while (t >= tileofs_s[r + 1]) r++;
            g_tile_rel[t]  = r;
            g_tile_base[t] = relofs_s[r] + (t - tileofs_s[r]) * TILE;
        } else {
            g_tile_rel[t] = -1;
        }
    }
}

// ---------------------------------------------------------------------------
__global__ void k_scatter(const int* __restrict__ src, const int* __restrict__ dst,
                          const int* __restrict__ et, int E, int chunk) {
    __shared__ int cur[16];
    if (threadIdx.x < 16)
        cur[threadIdx.x] = g_relofs[threadIdx.x] +
                           g_blockcounts[blockIdx.x * 16 + threadIdx.x];
    __syncthreads();
    int lo = blockIdx.x * chunk, hi = min(E, lo + chunk);
    for (int e = lo + threadIdx.x; e < hi; e += blockDim.x) {
        int r = et[e];
        int pos = atomicAdd(&cur[r], 1);
        g_edge[pos] = make_int2(src[e], dst[e]);   // one 8B store (1 sector)
    }
}

// ---------------------------------------------------------------------------
// fp16 m16n8k16 HMMA (sm_80+ portable)
#define MMA_F16(d, a, b)                                                      \
    asm volatile(                                                             \
        "mma.sync.aligned.m16n8k16.row.col.f32.f16.f16.f32 "                  \
        "{%0,%1,%2,%3}, {%4,%5,%6,%7}, {%8,%9}, {%0,%1,%2,%3};"               \
        : "+f"((d)[0]), "+f"((d)[1]), "+f"((d)[2]), "+f"((d)[3])              \
        : "r"((a)[0]), "r"((a)[1]), "r"((a)[2]), "r"((a)[3]),                 \
          "r"((b)[0]), "r"((b)[1]))

#define CPA16(saddr, gaddr, ssz)                                              \
    asm volatile("cp.async.cg.shared.global [%0], [%1], 16, %2;"              \
                 :: "r"(saddr), "l"(gaddr), "r"(ssz))

// smem layout (bytes):
//   stage s (s=0,1) at s*16384: A 128 rows x 128 B, XOR-swizzled
//     (16B chunk ch of row r stored at r*128 + ((ch ^ (r&7))<<4))
//   Bh  at 32768 (64x72 halves = 9216, padded stride kept)
//   dsh at 41984 (2 stages x 128 int = 1024)
#define STAGE_BYTES 16384
#define SM_BHI  32768
#define SM_DST  41984
#define SMEM_DYN 43008
#define BSTRIDE 72           // halves per B row

__global__ __launch_bounds__(BLK, 5) void k_rgcn_mma(float* __restrict__ out) {
    extern __shared__ char smb[];
    unsigned short* Bh = (unsigned short*)(smb + SM_BHI);
    int* dsh = (int*)(smb + SM_DST);

    int tid = threadIdx.x, w = tid >> 5, lane = tid & 31;
    int g = lane >> 2, tig = lane & 3;

    uint32_t smbase;
    asm("{ .reg .u64 t; cvta.to.shared.u64 t, %1; cvt.u32.u64 %0, t; }"
        : "=r"(smbase) : "l"(smb));

    int per = (MAXT + GRID_MMA - 1) / GRID_MMA;
    int t0 = blockIdx.x * per, t1 = min(MAXT, t0 + per);
    int cur_rel = -1;

    // ---- prefetch tile tt into stage st: 8 lanes cooperate per feat row;
    //      chunk ch stored XOR-swizzled so dense 128B rows stay
    //      bank-conflict-free for fragment reads. ----
    int rsub = tid >> 3, ch = tid & 7;     // rsub: 0..15, ch: 0..7 (16B chunk)
    auto issue = [&](int tt, int st, int reln) {
        int bs = g_tile_base[tt];
        int nn = min(TILE, g_relofs[reln + 1] - bs);
        #pragma unroll
        for (int it = 0; it < 8; it++) {
            int row = it * 16 + rsub;
            int ok = row < nn;
            int2 e = ok ? g_edge[bs + row] : make_int2(0, -1);
            if (ch == 0) dsh[st * TILE + row] = ok ? e.y : -1;
            unsigned ssz = ok ? 16u : 0u;
            uint32_t d = smbase + st * STAGE_BYTES + row * 128 +
                         ((ch ^ (row & 7)) << 4);
            CPA16(d, (const char*)g_fh + (size_t)e.x * 128 + ch * 16, ssz);
        }
    };

    // prologue: prefetch first tile into stage t0&1 (parity-correct)
    {
        int rel0 = (t0 < t1) ? g_tile_rel[t0] : -1;
        if (rel0 >= 0) issue(t0, t0 & 1, rel0);
        asm volatile("cp.async.commit_group;" ::: "memory");
    }

    for (int t = t0; t < t1; t++) {
        int rel = g_tile_rel[t];
        if (rel < 0) break;
        int st = t & 1;

        asm volatile("cp.async.wait_group 0;" ::: "memory");
        __syncthreads();   // stage st ready everywhere; all done with t-1

        // prefetch tile t+1 into the stage just vacated
        {
            int tn = t + 1;
            int reln = (tn < t1) ? g_tile_rel[tn] : -1;
            if (reln >= 0) issue(tn, tn & 1, reln);
            asm volatile("cp.async.commit_group;" ::: "memory");
        }

        // B reload on relation change (rare: ~1-2 per CTA range)
        if (rel != cur_rel) {
            cur_rel = rel;
            #pragma unroll
            for (int c = 0; c < 4; c++) {
                int p8  = tid + c * BLK;            // 512 uint4 chunks
                int idx = p8 * 8;
                int nr = idx >> 6, k = idx & 63;
                *(uint4*)(Bh + nr * BSTRIDE + k) =
                    *(const uint4*)(g_Bh + rel * 4096 + idx);
            }
            __syncthreads();
        }

        const char* As = smb + st * STAGE_BYTES;
        const int* dshs = dsh + st * TILE;

        // GEMM: warp w owns rows [32w,32w+32) = 2 m16 x 8 n8 blocks, 1 pass
        float acc[2][8][4];
        #pragma unroll
        for (int m = 0; m < 2; m++)
            #pragma unroll
            for (int nb = 0; nb < 8; nb++)
                #pragma unroll
                for (int j = 0; j < 4; j++) acc[m][nb][j] = 0.f;

        #pragma unroll
        for (int ks = 0; ks < 4; ks++) {
            // A fragment: row r, k-halves [16ks+2tig, +1] and [+8].
            // byte in row = 32ks + 4tig (+16). chunk = 2ks (+1), swz ^= (r&7)=g
            int c0 = ((2 * ks) ^ g) << 4, c1 = ((2 * ks + 1) ^ g) << 4;
            unsigned ah[2][4];
            #pragma unroll
            for (int m = 0; m < 2; m++) {
                const char* r0 = As + (32 * w + 16 * m + g) * 128 + tig * 4;
                const char* r1 = r0 + 8 * 128;
                ah[m][0] = *(const unsigned*)(r0 + c0);
                ah[m][1] = *(const unsigned*)(r1 + c0);
                ah[m][2] = *(const unsigned*)(r0 + c1);
                ah[m][3] = *(const unsigned*)(r1 + c1);
            }
            int kc = ks * 16 + 2 * tig;
            #pragma unroll
            for (int nb = 0; nb < 8; nb++) {
                int b0 = (8 * nb + g) * BSTRIDE + kc;
                unsigned bh[2];
                bh[0] = *(const unsigned*)(Bh + b0);
                bh[1] = *(const unsigned*)(Bh + b0 + 8);
                #pragma unroll
                for (int m = 0; m < 2; m++)
                    MMA_F16(acc[m][nb], ah[m], bh);
            }
        }

        // epilogue: partner-lane (lane^1) shfl -> red.v4, no smem staging
        #pragma unroll
        for (int m = 0; m < 2; m++) {
            int r0 = 32 * w + 16 * m + g;
            int dn0 = dshs[r0];
            int dn1 = dshs[r0 + 8];
            #pragma unroll
            for (int nb = 0; nb < 8; nb++) {
                float c0 = acc[m][nb][0], c1 = acc[m][nb][1];
                float c2 = acc[m][nb][2], c3 = acc[m][nb][3];
                float e0 = __shfl_xor_sync(0xffffffffu, c0, 1);
                float e1 = __shfl_xor_sync(0xffffffffu, c1, 1);
                float e2 = __shfl_xor_sync(0xffffffffu, c2, 1);
                float e3 = __shfl_xor_sync(0xffffffffu, c3, 1);
                if (tig & 1) {
                    if (dn1 >= 0) {
                        float* op = out + (long long)dn1 * 64 + 8 * nb + 2 * (tig - 1);
                        asm volatile("red.global.add.v4.f32 [%0], {%1, %2, %3, %4};"
                                     :: "l"(op), "f"(e2), "f"(e3), "f"(c2), "f"(c3)
                                     : "memory");
                    }
                } else {
                    if (dn0 >= 0) {
                        float* op = out + (long long)dn0 * 64 + 8 * nb + 2 * tig;
                        asm volatile("red.global.add.v4.f32 [%0], {%1, %2, %3, %4};"
                                     :: "l"(op), "f"(c0), "f"(c1), "f"(e0), "f"(e1)
                                     : "memory");
                    }
                }
            }
        }
        // no trailing barrier: next iteration's wait+syncthreads protects reuse
    }
}

// ---------------------------------------------------------------------------
extern "C" void kernel_launch(void* const* d_in, const int* in_sizes, int n_in,
                              void* d_out, int out_size) {
    const float* feat   = (const float*)d_in[0];   // [N, 64]
    const float* weight = (const float*)d_in[1];   // [16, 64, 64]
    const int*   src    = (const int*)d_in[2];     // [E]
    const int*   dst    = (const int*)d_in[3];     // [E]
    const int*   etyp   = (const int*)d_in[4];     // [E]
    float*       out    = (float*)d_out;           // [N, 64]

    int E = in_sizes[2];
    int n4 = out_size >> 2;
    int chunk = (E + NB_SORT - 1) / NB_SORT;

    cudaFuncSetAttribute(k_rgcn_mma, cudaFuncAttributeMaxDynamicSharedMemorySize,
                         SMEM_DYN);

    k_prep<<<NB_SORT, 256>>>((float4*)out, n4, weight, feat, etyp, E, chunk);
    k_scan<<<1, 512>>>();
    k_scatter<<<NB_SORT, 256>>>(src, dst, etyp, E, chunk);
    k_rgcn_mma<<<GRID_MMA, BLK, SMEM_DYN>>>(out);
}